// round 2
// baseline (speedup 1.0000x reference)
#include <cuda_runtime.h>
#include <cuda_fp16.h>
#include <cstdint>

#define GN 4096
#define DIN 64
#define DOUT 64
#define TOPK 4
#define SCALE 2048.0f
#define SCALE2 (2048.0f*2048.0f)

// ---------------- scratch (static device globals; no allocs allowed) --------
__device__ __half g_Sh [GN*(size_t)GN];   // S*SCALE, row-major  [i][k]  (32MB)
__device__ __half g_ShT[GN*(size_t)GN];   // S^T*SCALE, row-major [j][k] (32MB)
__device__ float  g_S2 [GN*(size_t)GN];   // (S*SCALE)@(S*SCALE)          (64MB)
__device__ float  g_dinv[GN];
__device__ float  g_rS[GN];
__device__ float  g_rs2[GN];
__device__ float  g_dinv2[GN];
__device__ float  g_t[2];
__device__ float  g_y[GN*DOUT];

// ---------------- small helpers --------------------------------------------
__device__ __forceinline__ float blk_reduce_sum(float s) {
    __shared__ float sm[8];
    for (int o = 16; o; o >>= 1) s += __shfl_down_sync(0xffffffffu, s, o);
    if ((threadIdx.x & 31) == 0) sm[threadIdx.x >> 5] = s;
    __syncthreads();
    float v = 0.f;
    if (threadIdx.x < 8) {
        v = sm[threadIdx.x];
        for (int o = 4; o; o >>= 1) v += __shfl_down_sync(0xffu, v, o);
    }
    return v;  // valid in thread 0
}

// d[i] = sum_j A[i,j];  g_dinv[i] = rsqrt(d)
__global__ void k_rowsumA(const float* __restrict__ A) {
    int row = blockIdx.x;
    const float4* Ar = reinterpret_cast<const float4*>(A + (size_t)row * GN);
    float s = 0.f;
    for (int j = threadIdx.x; j < GN / 4; j += blockDim.x) {
        float4 v = Ar[j];
        s += v.x + v.y + v.z + v.w;
    }
    float tot = blk_reduce_sum(s);
    if (threadIdx.x == 0) g_dinv[row] = rsqrtf(tot);
}

// g_rS[i] = rowsum(S)[i] = dinv[i] * sum_j A[i,j]*dinv[j]
__global__ void k_rowsumS(const float* __restrict__ A) {
    int row = blockIdx.x;
    const float4* Ar = reinterpret_cast<const float4*>(A + (size_t)row * GN);
    const float4* Dv = reinterpret_cast<const float4*>(g_dinv);
    float s = 0.f;
    for (int j = threadIdx.x; j < GN / 4; j += blockDim.x) {
        float4 a = Ar[j];
        float4 d = Dv[j];
        s += a.x * d.x + a.y * d.y + a.z * d.z + a.w * d.w;
    }
    float tot = blk_reduce_sum(s);
    if (threadIdx.x == 0) g_rS[row] = g_dinv[row] * tot;
}

// build Sh (row-major) and ShT (transposed) in fp16, scaled by SCALE
__global__ void k_build(const float* __restrict__ A) {
    __shared__ float tile[32][33];
    int bx = blockIdx.x, by = blockIdx.y;
    int tx = threadIdx.x, ty = threadIdx.y;
    int col = bx * 32 + tx;
    float dc = g_dinv[col];
#pragma unroll
    for (int r = 0; r < 4; r++) {
        int row = by * 32 + ty + r * 8;
        float v = A[(size_t)row * GN + col] * g_dinv[row] * dc * SCALE;
        tile[ty + r * 8][tx] = v;
        g_Sh[(size_t)row * GN + col] = __float2half_rn(v);
    }
    __syncthreads();
#pragma unroll
    for (int r = 0; r < 4; r++) {
        int orow = bx * 32 + ty + r * 8;  // j
        int ocol = by * 32 + tx;          // i
        g_ShT[(size_t)orow * GN + ocol] = __float2half_rn(tile[tx][ty + r * 8]);
    }
}

// ---------------- fp16 tensor-core GEMM: C = Sh @ ShT^T ---------------------
// CTA tile 128x128, K-chunk 32, 8 warps (warp tile 32x64), double-buffered cp.async
#define TKC 32
__global__ void __launch_bounds__(256) k_gemm() {
    __shared__ __half As[2][128][40];
    __shared__ __half Bs[2][128][40];
    const __half* Ag = g_Sh;
    const __half* Bg = g_ShT;
    int tid = threadIdx.x;
    int warp = tid >> 5, lane = tid & 31;
    int wm = warp & 3;   // 0..3 -> 32-row slab
    int wn = warp >> 2;  // 0..1 -> 64-col slab
    int rowBase = blockIdx.y * 128;
    int colBase = blockIdx.x * 128;

    float acc[2][8][4];
#pragma unroll
    for (int a = 0; a < 2; a++)
#pragma unroll
        for (int b = 0; b < 8; b++)
#pragma unroll
            for (int c = 0; c < 4; c++) acc[a][b][c] = 0.f;

    auto loadTiles = [&](int buf, int k0) {
#pragma unroll
        for (int it = 0; it < 2; it++) {
            int lin = tid + it * 256;          // 0..511
            int r   = lin >> 2;                // 0..127
            int c8  = (lin & 3) * 8;           // 0,8,16,24
            const __half* ga = Ag + (size_t)(rowBase + r) * GN + k0 + c8;
            uint32_t sa = (uint32_t)__cvta_generic_to_shared(&As[buf][r][c8]);
            asm volatile("cp.async.cg.shared.global [%0],[%1],16;\n" :: "r"(sa), "l"(ga));
            const __half* gb = Bg + (size_t)(colBase + r) * GN + k0 + c8;
            uint32_t sb = (uint32_t)__cvta_generic_to_shared(&Bs[buf][r][c8]);
            asm volatile("cp.async.cg.shared.global [%0],[%1],16;\n" :: "r"(sb), "l"(gb));
        }
        asm volatile("cp.async.commit_group;\n");
    };

    loadTiles(0, 0);
    asm volatile("cp.async.wait_group 0;\n");
    __syncthreads();

    int buf = 0;
    const int NK = GN / TKC;  // 128
    for (int kt = 0; kt < NK; kt++) {
        if (kt + 1 < NK) loadTiles(buf ^ 1, (kt + 1) * TKC);
#pragma unroll
        for (int ks = 0; ks < 2; ks++) {
            int kk = ks * 16;
            uint32_t af[2][4];
#pragma unroll
            for (int mt = 0; mt < 2; mt++) {
                int m  = wm * 32 + mt * 16 + (lane & 15);
                int kc = kk + (lane >> 4) * 8;
                uint32_t addr = (uint32_t)__cvta_generic_to_shared(&As[buf][m][kc]);
                asm volatile("ldmatrix.sync.aligned.m8n8.x4.shared.b16 {%0,%1,%2,%3},[%4];"
                             : "=r"(af[mt][0]), "=r"(af[mt][1]), "=r"(af[mt][2]), "=r"(af[mt][3])
                             : "r"(addr));
            }
            uint32_t bf[8][2];
#pragma unroll
            for (int nb = 0; nb < 4; nb++) {
                int sel = lane >> 3;
                int nn  = wn * 64 + nb * 16 + (sel >> 1) * 8 + (lane & 7);
                int kc  = kk + (sel & 1) * 8;
                uint32_t addr = (uint32_t)__cvta_generic_to_shared(&Bs[buf][nn][kc]);
                uint32_t r0, r1, r2, r3;
                asm volatile("ldmatrix.sync.aligned.m8n8.x4.shared.b16 {%0,%1,%2,%3},[%4];"
                             : "=r"(r0), "=r"(r1), "=r"(r2), "=r"(r3) : "r"(addr));
                bf[nb * 2][0] = r0; bf[nb * 2][1] = r1;
                bf[nb * 2 + 1][0] = r2; bf[nb * 2 + 1][1] = r3;
            }
#pragma unroll
            for (int mt = 0; mt < 2; mt++)
#pragma unroll
                for (int nt = 0; nt < 8; nt++) {
                    asm volatile(
                        "mma.sync.aligned.m16n8k16.row.col.f32.f16.f16.f32 "
                        "{%0,%1,%2,%3},{%4,%5,%6,%7},{%8,%9},{%0,%1,%2,%3};"
                        : "+f"(acc[mt][nt][0]), "+f"(acc[mt][nt][1]),
                          "+f"(acc[mt][nt][2]), "+f"(acc[mt][nt][3])
                        : "r"(af[mt][0]), "r"(af[mt][1]), "r"(af[mt][2]), "r"(af[mt][3]),
                          "r"(bf[nt][0]), "r"(bf[nt][1]));
                }
        }
        if (kt + 1 < NK) asm volatile("cp.async.wait_group 0;\n");
        __syncthreads();
        buf ^= 1;
    }

    // epilogue: c0,c1 -> (m=lane/4, n=2*(lane%4)+{0,1}); c2,c3 -> m+8
#pragma unroll
    for (int mt = 0; mt < 2; mt++)
#pragma unroll
        for (int nt = 0; nt < 8; nt++) {
            int m0 = rowBase + wm * 32 + mt * 16 + (lane >> 2);
            int n0 = colBase + wn * 64 + nt * 8 + (lane & 3) * 2;
            *reinterpret_cast<float2*>(g_S2 + (size_t)m0 * GN + n0) =
                make_float2(acc[mt][nt][0], acc[mt][nt][1]);
            *reinterpret_cast<float2*>(g_S2 + (size_t)(m0 + 8) * GN + n0) =
                make_float2(acc[mt][nt][2], acc[mt][nt][3]);
        }
}

// rowsum of S^2 (unscaled)
__global__ void k_rowsumS2() {
    int row = blockIdx.x;
    const float4* Sr = reinterpret_cast<const float4*>(g_S2 + (size_t)row * GN);
    float s = 0.f;
    for (int j = threadIdx.x; j < GN / 4; j += blockDim.x) {
        float4 v = Sr[j];
        s += v.x + v.y + v.z + v.w;
    }
    float tot = blk_reduce_sum(s);
    if (threadIdx.x == 0) g_rs2[row] = tot * (1.0f / SCALE2);
}

__global__ void k_sig(const float* __restrict__ theta) {
    if (threadIdx.x < 2) g_t[threadIdx.x] = 1.0f / (1.0f + expf(-theta[threadIdx.x]));
}

__global__ void k_d2() {
    int i = blockIdx.x * blockDim.x + threadIdx.x;
    if (i < GN) {
        float d2 = 1.0f + g_t[0] * g_rS[i] + g_t[1] * g_rs2[i];
        g_dinv2[i] = rsqrtf(d2);
    }
}

// y = x @ W^T   (per-row block, W staged transposed in smem)
__global__ void k_xw(const float* __restrict__ x, const float* __restrict__ W) {
    __shared__ float Wt[DIN * DOUT];  // Wt[d*DOUT + c] = W[c*DIN + d]
    __shared__ float xr[DIN];
    int row = blockIdx.x;
    for (int i = threadIdx.x; i < DOUT * DIN; i += 64) {
        int c = i / DIN, d = i % DIN;
        Wt[d * DOUT + c] = W[i];
    }
    if (threadIdx.x < DIN) xr[threadIdx.x] = x[row * DIN + threadIdx.x];
    __syncthreads();
    int c = threadIdx.x;
    float s = 0.f;
#pragma unroll
    for (int d = 0; d < DIN; d++) s += xr[d] * Wt[d * DOUT + c];
    g_y[row * DOUT + c] = s;
}

// ---------------- top-4 per row + sparse output -----------------------------
__device__ __forceinline__ void topk_insert(float c, int j, float* v, int* id) {
    if (c > v[3] || (c == v[3] && j < id[3])) {
        v[3] = c; id[3] = j;
#pragma unroll
        for (int s = 3; s > 0; s--) {
            if (v[s] > v[s - 1] || (v[s] == v[s - 1] && id[s] < id[s - 1])) {
                float tv = v[s]; v[s] = v[s - 1]; v[s - 1] = tv;
                int ti = id[s]; id[s] = id[s - 1]; id[s - 1] = ti;
            }
        }
    }
}

__global__ void k_topk(const float* __restrict__ A, const float* __restrict__ b,
                       float* __restrict__ out) {
    int i   = blockIdx.x;
    int tid = threadIdx.x;
    float t0  = g_t[0];
    float t1s = g_t[1] * (1.0f / SCALE2);
    float di  = g_dinv[i];
    const float* Ar = A    + (size_t)i * GN;
    const float* Sr = g_S2 + (size_t)i * GN;

    float vb[4] = {-1e30f, -1e30f, -1e30f, -1e30f};
    int   ib[4] = {0x7fffffff, 0x7fffffff, 0x7fffffff, 0x7fffffff};

    for (int j = tid; j < GN; j += 128) {
        float p = t0 * (Ar[j] * di * g_dinv[j]) + t1s * Sr[j];
        if (j == i) p += 1.0f;
        float c = p * g_dinv2[j];
        topk_insert(c, j, vb, ib);
    }

    __shared__ float sv[128 * 4];
    __shared__ int   si[128 * 4];
#pragma unroll
    for (int s = 0; s < 4; s++) { sv[tid * 4 + s] = vb[s]; si[tid * 4 + s] = ib[s]; }
    __syncthreads();

    __shared__ float fv[4];
    __shared__ int   fi[4];
    if (tid == 0) {
        float bv[4] = {-1e30f, -1e30f, -1e30f, -1e30f};
        int   bi[4] = {0x7fffffff, 0x7fffffff, 0x7fffffff, 0x7fffffff};
        for (int q = 0; q < 128 * 4; q++) topk_insert(sv[q], si[q], bv, bi);
#pragma unroll
        for (int s = 0; s < 4; s++) { fv[s] = bv[s]; fi[s] = bi[s]; }
    }
    __syncthreads();

    if (tid < DOUT) {
        float di2 = g_dinv2[i];
        float s = b[tid];
#pragma unroll
        for (int q = 0; q < TOPK; q++)
            s += di2 * fv[q] * g_y[fi[q] * DOUT + tid];
        out[(size_t)i * DOUT + tid] = s;
    }
}

// ---------------- launch -----------------------------------------------------
extern "C" void kernel_launch(void* const* d_in, const int* in_sizes, int n_in,
                              void* d_out, int out_size) {
    const float* x     = (const float*)d_in[0];
    const float* A     = (const float*)d_in[1];
    const float* theta = (const float*)d_in[2];
    const float* W     = (const float*)d_in[3];
    const float* b     = (const float*)d_in[4];
    float* out = (float*)d_out;

    k_rowsumA<<<GN, 256>>>(A);
    k_sig<<<1, 32>>>(theta);
    k_rowsumS<<<GN, 256>>>(A);
    k_build<<<dim3(128, 128), dim3(32, 8)>>>(A);
    k_gemm<<<dim3(32, 32), 256>>>();
    k_rowsumS2<<<GN, 256>>>();
    k_d2<<<16, 256>>>();
    k_xw<<<GN, 64>>>(x, W);
    k_topk<<<GN, 128>>>(A, b, out);
}